// round 14
// baseline (speedup 1.0000x reference)
#include <cuda_runtime.h>
#include <cstdint>

// Problem constants
#define BATCH   32
#define PLEN    1024
#define DIM     8
#define SIGLEN  4680        // 8 + 64 + 512 + 4096
#define LVL2_OFF 8
#define LVL3_OFF 72
#define LVL4_OFF 584
#define GROUPS   4          // groups per batch; each group = 8 chunks of 32 incs

// Dynamic smem layout (bytes)
#define S4_BYTES   (8 * 2048 * 8)            // 8 chunks x 2048 u64 (L4)  = 131072
#define SL_OFF     (S4_BYTES)                // L1..L3 per chunk: 8 x 584 floats
#define SL_BYTES   (8 * 584 * 4)             // 18688
#define SX_OFF     (SL_OFF + SL_BYTES)       // increments: 2048 floats
#define SX_BYTES   (2048 * 4)                // 8192
#define SMEM_TOTAL_BYTES (SX_OFF + SX_BYTES) // 157952

// Scratch (device globals — no cudaMalloc allowed)
__device__ float g_buf1[BATCH * GROUPS * SIGLEN];   // partial sigs (slots 1,2,3 used)
__device__ int   g_flags[BATCH * 4];                // per-batch flags; reset by consumers

typedef unsigned long long u64;

// ---- packed f32x2 helpers -------------------------------------------------
__device__ __forceinline__ u64 fma2(u64 a, u64 b, u64 c)
{
    u64 d;
    asm("fma.rn.f32x2 %0, %1, %2, %3;" : "=l"(d) : "l"(a), "l"(b), "l"(c));
    return d;
}
__device__ __forceinline__ u64 dup2(float x)
{
    u64 d;
    asm("mov.b64 %0, {%1, %1};" : "=l"(d) : "f"(x));
    return d;
}
__device__ __forceinline__ float2 unpack2(u64 v)
{
    float2 f;
    asm("mov.b64 {%0, %1}, %2;" : "=f"(f.x), "=f"(f.y) : "l"(v));
    return f;
}

// ---- tail helpers ----------------------------------------------------------
// Stage one partial signature: levels 1..3 into sL (t<146 threads, float4),
// level 4 slice into registers (all threads, MLP front-batched by caller order).
__device__ __forceinline__ void stage_partial(
    const float* __restrict__ Bp, float* sL, int t, float4& lo, float4& hi)
{
    if (t < 146) {
        const float4* Bp4 = reinterpret_cast<const float4*>(Bp);
        reinterpret_cast<float4*>(sL)[t] = __ldcg(Bp4 + t);   // 146*16B = L1..L3
    }
    const float4* B4 = reinterpret_cast<const float4*>(Bp + LVL4_OFF);
    lo = __ldcg(B4 + 2 * t);
    hi = __ldcg(B4 + 2 * t + 1);
}

// One Chen right-multiply C = C (x) B, B levels 1..3 in sL[0..584), B level-4
// slice in (lo,hi). Proven arithmetic (identical order to prior rounds).
__device__ __forceinline__ void chen_mul(
    const float* B, float4 lo, float4 hi,
    float c4[8], float& c3, float& a2r, float& a1r,
    int t, int p2, int q2, int r2, int pq2, int qr2)
{
    float b4[8] = {lo.x, lo.y, lo.z, lo.w, hi.x, hi.y, hi.z, hi.w};

    const float4* b3s = reinterpret_cast<const float4*>(B + LVL3_OFF + qr2 * 8);
    const float4* b2s = reinterpret_cast<const float4*>(B + LVL2_OFF + r2 * 8);
    const float4* b1s = reinterpret_cast<const float4*>(B);
    float4 w3a = b3s[0], w3b = b3s[1];
    float4 w2a = b2s[0], w2b = b2s[1];
    float4 w1a = b1s[0], w1b = b1s[1];
    float b3a[8] = {w3a.x,w3a.y,w3a.z,w3a.w,w3b.x,w3b.y,w3b.z,w3b.w};
    float b2a[8] = {w2a.x,w2a.y,w2a.z,w2a.w,w2b.x,w2b.y,w2b.z,w2b.w};
    float b1a[8] = {w1a.x,w1a.y,w1a.z,w1a.w,w1b.x,w1b.y,w1b.z,w1b.w};

    #pragma unroll
    for (int s = 0; s < 8; ++s) {
        float cc = c4[s] + b4[s];
        cc = fmaf(a1r, b3a[s], cc);
        cc = fmaf(a2r, b2a[s], cc);
        cc = fmaf(c3,  b1a[s], cc);   // OLD c3
        c4[s] = cc;
    }

    float b3t  = B[LVL3_OFF + t];
    float b2qr = B[LVL2_OFF + qr2];
    float b2pq = B[LVL2_OFF + pq2];
    float b1r  = B[r2];
    float b1q  = B[q2];
    float b1p  = B[p2];

    float nc3 = c3 + b3t + a1r * b2qr + a2r * b1r;   // old a1, a2
    float na2 = a2r + b2pq + a1r * b1q;              // old a1
    float na1 = a1r + b1p;
    c3 = nc3; a2r = na2; a1r = na1;
}

// Publish a signature held in registers to a partials slot.
__device__ __forceinline__ void publish_partial(
    float* O, const float c4[8], float c3, float a2r, float a1r,
    int t, int p2, int r2, int pq2)
{
    if ((t & 63) == 0) O[p2] = a1r;
    if (r2 == 0)       O[LVL2_OFF + pq2] = a2r;
    O[LVL3_OFF + t] = c3;
    float4* O4 = reinterpret_cast<float4*>(O + LVL4_OFF);
    O4[2 * t]     = make_float4(c4[0], c4[1], c4[2], c4[3]);
    O4[2 * t + 1] = make_float4(c4[4], c4[5], c4[6], c4[7]);
}

__device__ __forceinline__ void wait_and_clear(int* flag)
{
    while (atomicAdd(flag, 0) == 0) __nanosleep(16);
    *flag = 0;            // reset for next graph replay
    __threadfence();
}

// ---------------------------------------------------------------------------
// Single persistent kernel.
// Phase 1: 8 chunk signatures per block, one (p,q) row per thread (s-pair
//          f32x2 packing, unroll-4). Level-1 telescope LDGs hoisted early.
// Phase 2: barrier-free in-block Chen reduction of the 8 chunk sigs.
// Phase 3: parallel-tree handoff: g1,g3 publish; g2 combines P2*P3 and
//          publishes; g0 combines P0*P1 (overlapped with g2) then *P23.
//          Grid = 128 blocks, all co-resident -> no deadlock.
// ---------------------------------------------------------------------------
__global__ __launch_bounds__(512) void sig_onekernel(
    const float* __restrict__ path, float* __restrict__ partials,
    int* __restrict__ flags, float* __restrict__ out)
{
    extern __shared__ __align__(16) char smem[];
    u64*   s4 = reinterpret_cast<u64*>(smem);
    float* sL = reinterpret_cast<float*>(smem + SL_OFF);
    float* sx = reinterpret_cast<float*>(smem + SX_OFF);

    const int bx = blockIdx.x;
    const int b  = bx >> 2;
    const int g  = bx & 3;
    const int t  = threadIdx.x;
    const int sc  = t >> 6;      // chunk within group (0..7)
    const int tpq = t & 63;      // (p,q) row within chunk
    const int p   = tpq >> 3;
    const int q   = tpq & 7;

    const float* pb = path + (size_t)b * (PLEN * DIM);

    // ---- load this group's 256 increments (vectorized: 2 LDG.128/thread) ----
    {
        const float4* pb4 = reinterpret_cast<const float4*>(pb);
        int j = t;                       // one float4 per thread (512 total)
        int i = g * 256 + (j >> 1);      // increment index
        int half = j & 1;                // which 4 dims
        float4 v = make_float4(0.f, 0.f, 0.f, 0.f);
        if (i < PLEN - 1) {
            float4 hi = pb4[(i + 1) * 2 + half];
            float4 lo = pb4[i * 2 + half];
            v = make_float4(hi.x - lo.x, hi.y - lo.y, hi.z - lo.z, hi.w - lo.w);
        }
        reinterpret_cast<float4*>(sx)[j] = v;
    }

    // hoisted level-1 telescope (LDGs issued ~whole phase-1 early)
    float l1v = 0.0f;
    if (tpq < 8) {
        int c  = g * 8 + sc;
        int i0 = c * 32;
        int i1 = min(i0 + 32, PLEN - 1);
        l1v = pb[i1 * 8 + tpq] - pb[i0 * 8 + tpq];
    }
    __syncthreads();

    const float* sxc = sx + sc * 256;

    // ---- phase 1: chunk signature, 64 L4 entries per thread ----
    u64 P[32];          // a4[r][s-pair j], idx = r*4+j
    #pragma unroll
    for (int i = 0; i < 32; ++i) P[i] = 0ull;
    u64 A3[4] = {0ull, 0ull, 0ull, 0ull};  // a3 pairs (2rp,2rp+1)
    float a2 = 0.f, a1p = 0.f;

    #pragma unroll 4
    for (int k = 0; k < 32; ++k) {
        ulonglong2 xa = *reinterpret_cast<const ulonglong2*>(sxc + k * 8);
        ulonglong2 xb = *reinterpret_cast<const ulonglong2*>(sxc + k * 8 + 4);
        u64 Xv[4] = {xa.x, xa.y, xb.x, xb.y};
        float xp = sxc[k * 8 + p];
        float xq = sxc[k * 8 + q];

        // shared scalar chain (OLD state)
        float v      = fmaf(xp, (1.0f/24.0f), a1p * (1.0f/6.0f));
        float inner  = fmaf(xq, v, a2 * 0.5f);
        float w      = fmaf(xp, (1.0f/6.0f), a1p * 0.5f);
        float innerW = fmaf(xq, w, a2);
        a2  = fmaf(xq, fmaf(xp, 0.5f, a1p), a2);
        a1p += xp;

        u64 inner2  = dup2(inner);
        u64 innerW2 = dup2(innerW);

        #pragma unroll
        for (int rp = 0; rp < 4; ++rp) {
            u64 t4p = fma2(Xv[rp], inner2, A3[rp]);   // OLD a3 pair
            A3[rp]  = fma2(Xv[rp], innerW2, A3[rp]);
            float2 tt = unpack2(t4p);
            u64 tlo = dup2(tt.x);
            u64 thi = dup2(tt.y);
            #pragma unroll
            for (int j = 0; j < 4; ++j)
                P[(2 * rp) * 4 + j] = fma2(Xv[j], tlo, P[(2 * rp) * 4 + j]);
            #pragma unroll
            for (int j = 0; j < 4; ++j)
                P[(2 * rp + 1) * 4 + j] = fma2(Xv[j], thi, P[(2 * rp + 1) * 4 + j]);
        }
    }

    // ---- store chunk signature into smem ----
    float* L = sL + sc * 584;
    if (tpq < 8) L[tpq] = l1v;           // telescoped level-1 (hoisted)
    L[LVL2_OFF + tpq] = a2;
    #pragma unroll
    for (int rp = 0; rp < 4; ++rp) {
        float2 a3v = unpack2(A3[rp]);
        L[LVL3_OFF + tpq * 8 + 2 * rp]     = a3v.x;
        L[LVL3_OFF + tpq * 8 + 2 * rp + 1] = a3v.y;
    }
    {
        u64* s4c = s4 + sc * 2048 + tpq * 32;
        int sw = tpq & 31;
        #pragma unroll
        for (int idx = 0; idx < 32; ++idx) s4c[idx ^ sw] = P[idx];
    }
    __syncthreads();

    // ---- phase 2: barrier-free Chen reduction of 8 chunk sigs ----
    const int p2  = t >> 6;
    const int q2  = (t >> 3) & 7;
    const int r2  = t & 7;
    const int pq2 = t >> 3;
    const int qr2 = t & 63;
    const int swr = pq2 & 31;

    float c4[8];
    {
        const u64* bc = s4 + pq2 * 32;   // chunk 0
        #pragma unroll
        for (int j = 0; j < 4; ++j) {
            float2 vv = unpack2(bc[(r2 * 4 + j) ^ swr]);
            c4[2 * j]     = vv.x;
            c4[2 * j + 1] = vv.y;
        }
    }
    float c3  = sL[LVL3_OFF + t];
    float a2r = sL[LVL2_OFF + pq2];
    float a1r = sL[p2];

    // prefetch chunk 1's transposed L4 slice
    u64 nb[4];
    {
        const u64* bc = s4 + 2048 + pq2 * 32;
        #pragma unroll
        for (int j = 0; j < 4; ++j) nb[j] = bc[(r2 * 4 + j) ^ swr];
    }

    #pragma unroll 1
    for (int i = 1; i < 8; ++i) {
        float4 blo, bhi;
        {
            float2 v0 = unpack2(nb[0]);
            float2 v1 = unpack2(nb[1]);
            float2 v2 = unpack2(nb[2]);
            float2 v3 = unpack2(nb[3]);
            blo = make_float4(v0.x, v0.y, v1.x, v1.y);
            bhi = make_float4(v2.x, v2.y, v3.x, v3.y);
        }
        if (i + 1 < 8) {
            const u64* bc = s4 + (i + 1) * 2048 + pq2 * 32;
            #pragma unroll
            for (int j = 0; j < 4; ++j) nb[j] = bc[(r2 * 4 + j) ^ swr];
        }
        chen_mul(sL + i * 584, blo, bhi, c4, c3, a2r, a1r,
                 t, p2, q2, r2, pq2, qr2);
    }

    // ---- phase 3: parallel-tree handoff ----
    const float* PS = partials + (size_t)(b * GROUPS) * SIGLEN;
    float* PSm = partials + (size_t)(b * GROUPS) * SIGLEN;

    if (g == 1 || g == 3) {
        publish_partial(PSm + (size_t)g * SIGLEN, c4, c3, a2r, a1r, t, p2, r2, pq2);
        __threadfence();
        __syncthreads();
        if (t == 0) atomicExch(&flags[b * 4 + g], 1);
        return;
    }

    if (g == 2) {
        // combine own partial with g3's: P23 = P2 (x) P3
        if (t == 0) wait_and_clear(&flags[b * 4 + 3]);
        __syncthreads();
        float4 lo, hi;
        stage_partial(PS + (size_t)3 * SIGLEN, sL, t, lo, hi);
        __syncthreads();
        chen_mul(sL, lo, hi, c4, c3, a2r, a1r, t, p2, q2, r2, pq2, qr2);
        publish_partial(PSm + (size_t)2 * SIGLEN, c4, c3, a2r, a1r, t, p2, r2, pq2);
        __threadfence();
        __syncthreads();
        if (t == 0) atomicExch(&flags[b * 4 + 2], 1);
        return;
    }

    // g == 0 leader: P01 = P0 (x) P1 (overlaps g2's work), then (x) P23
    if (t == 0) wait_and_clear(&flags[b * 4 + 1]);
    __syncthreads();
    {
        float4 lo, hi;
        stage_partial(PS + (size_t)1 * SIGLEN, sL, t, lo, hi);
        __syncthreads();
        chen_mul(sL, lo, hi, c4, c3, a2r, a1r, t, p2, q2, r2, pq2, qr2);
    }
    if (t == 0) wait_and_clear(&flags[b * 4 + 2]);
    __syncthreads();
    {
        float4 lo, hi;
        stage_partial(PS + (size_t)2 * SIGLEN, sL, t, lo, hi);
        __syncthreads();
        chen_mul(sL, lo, hi, c4, c3, a2r, a1r, t, p2, q2, r2, pq2, qr2);
    }

    // final output layout: [L1 32x8][L2 32x64][L3 32x512][L4 32x4096]
    float* o1 = out + (size_t)b * 8;
    float* o2 = out + 256   + (size_t)b * 64;
    float* o3 = out + 2304  + (size_t)b * 512;
    float* o4 = out + 18688 + (size_t)b * 4096;
    if ((t & 63) == 0) o1[p2] = a1r;
    if (r2 == 0)       o2[pq2] = a2r;
    o3[t] = c3;
    float4* O4 = reinterpret_cast<float4*>(o4);
    O4[2 * t]     = make_float4(c4[0], c4[1], c4[2], c4[3]);
    O4[2 * t + 1] = make_float4(c4[4], c4[5], c4[6], c4[7]);
}

// ---------------------------------------------------------------------------
extern "C" void kernel_launch(void* const* d_in, const int* in_sizes, int n_in,
                              void* d_out, int out_size)
{
    const float* path = (const float*)d_in[0];
    float* out = (float*)d_out;

    float* buf1;
    int* flags;
    cudaGetSymbolAddress((void**)&buf1, g_buf1);
    cudaGetSymbolAddress((void**)&flags, g_flags);

    cudaFuncSetAttribute(sig_onekernel,
                         cudaFuncAttributeMaxDynamicSharedMemorySize,
                         SMEM_TOTAL_BYTES);

    // single launch: chunk sigs + in-block reduce + parallel-tree handoff
    sig_onekernel<<<BATCH * GROUPS, 512, SMEM_TOTAL_BYTES>>>(path, buf1, flags, out);
}